// round 1
// baseline (speedup 1.0000x reference)
#include <cuda_runtime.h>

#define B_   32
#define C_   4
#define N_   16384
#define RES_ 32
#define NVOX (B_ * RES_ * RES_ * RES_)   // 1048576
#define NBLOCKS 2048                      // B_ * (N_/256)

// Scratch (allocation-free): padded float4 copy of voxel_grid_cp for 16B gathers.
__device__ float4 g_cp_pad[NVOX];         // 16 MB
__device__ float  g_partials[NBLOCKS];
__device__ float  g_reg;

// ---------------------------------------------------------------------------
// Pad voxel_grid_cp [B,32,32,32,3] -> float4 so the hot gather is one LDG.128.
// ---------------------------------------------------------------------------
__global__ void __launch_bounds__(256) pad_kernel(const float* __restrict__ cp) {
    int i = blockIdx.x * 256 + threadIdx.x;      // 0 .. NVOX-1
    const float* p = cp + (size_t)i * 3;
    g_cp_pad[i] = make_float4(p[0], p[1], p[2], 0.0f);
}

// ---------------------------------------------------------------------------
// Regularizer: 25 * mean_b || n_hat n_hat^T - I ||_F   (one warp, one lane/b)
// ---------------------------------------------------------------------------
__global__ void reg_kernel(const float* __restrict__ y_pred) {
    int b = threadIdx.x;                          // 32 threads
    const float* yp = y_pred + b * 16;
    float nh[4][3];
#pragma unroll
    for (int c = 0; c < 4; c++) {
        float nx = yp[c*4+0], ny = yp[c*4+1], nz = yp[c*4+2];
        float inv = rsqrtf(nx*nx + ny*ny + nz*nz);
        nh[c][0] = nx*inv; nh[c][1] = ny*inv; nh[c][2] = nz*inv;
    }
    float s = 0.0f;
#pragma unroll
    for (int c = 0; c < 4; c++)
#pragma unroll
        for (int e = 0; e < 4; e++) {
            float g = nh[c][0]*nh[e][0] + nh[c][1]*nh[e][1] + nh[c][2]*nh[e][2]
                      - (c == e ? 1.0f : 0.0f);
            s += g * g;
        }
    float reg = sqrtf(s);
#pragma unroll
    for (int off = 16; off >= 1; off >>= 1)
        reg += __shfl_xor_sync(0xffffffffu, reg, off);
    if (b == 0) g_reg = 25.0f * reg * (1.0f / (float)B_);
}

// ---------------------------------------------------------------------------
// Main: reflect each point through each of 4 planes, gather cp, sum norms.
// grid = B_ * N_/256 blocks of 256 threads; one n per thread, 4 planes inner.
// ---------------------------------------------------------------------------
__global__ void __launch_bounds__(256) refl_kernel(const float* __restrict__ y_pred,
                                                   const float* __restrict__ points) {
    int b = blockIdx.x >> 6;
    int n = ((blockIdx.x & 63) << 8) + threadIdx.x;

    __shared__ float4 plane[4];                   // n_hat.xyz, d
    if (threadIdx.x < 4) {
        const float* yp = y_pred + (b * 4 + threadIdx.x) * 4;
        float nx = yp[0], ny = yp[1], nz = yp[2];
        float inv = rsqrtf(nx*nx + ny*ny + nz*nz);
        plane[threadIdx.x] = make_float4(nx*inv, ny*inv, nz*inv, yp[3]);
    }
    __syncthreads();

    const float* pp = points + ((size_t)b * N_ + n) * 3;
    float px = pp[0], py = pp[1], pz = pp[2];

    const float4* cpb = g_cp_pad + (b << 15);     // b * 32768
    float acc = 0.0f;
#pragma unroll
    for (int c = 0; c < 4; c++) {
        float4 pl = plane[c];
        float t  = 2.0f * (px*pl.x + py*pl.y + pz*pl.z + pl.w);
        float rx = fmaf(-t, pl.x, px);
        float ry = fmaf(-t, pl.y, py);
        float rz = fmaf(-t, pl.z, pz);
        int v0 = min(RES_ - 1, max(0, __float2int_rd(rx * (float)RES_)));
        int v1 = min(RES_ - 1, max(0, __float2int_rd(ry * (float)RES_)));
        int v2 = min(RES_ - 1, max(0, __float2int_rd(rz * (float)RES_)));
        float4 cpv = __ldg(&cpb[(v0 << 10) | (v1 << 5) | v2]);
        float dx = rx - cpv.x, dy = ry - cpv.y, dz = rz - cpv.z;
        acc += sqrtf(fmaf(dx, dx, fmaf(dy, dy, dz * dz)));
    }

    // Deterministic block reduction (fixed order), no float atomics.
#pragma unroll
    for (int off = 16; off >= 1; off >>= 1)
        acc += __shfl_xor_sync(0xffffffffu, acc, off);
    __shared__ float ws[8];
    int wid = threadIdx.x >> 5;
    if ((threadIdx.x & 31) == 0) ws[wid] = acc;
    __syncthreads();
    if (threadIdx.x == 0) {
        float s = 0.0f;
#pragma unroll
        for (int w = 0; w < 8; w++) s += ws[w];
        g_partials[blockIdx.x] = s;
    }
}

// ---------------------------------------------------------------------------
// Final deterministic reduction: out = sum(partials)/N + reg
// ---------------------------------------------------------------------------
__global__ void __launch_bounds__(256) final_kernel(float* __restrict__ out) {
    __shared__ float s[256];
    float a = 0.0f;
    for (int i = threadIdx.x; i < NBLOCKS; i += 256) a += g_partials[i];
    s[threadIdx.x] = a;
    __syncthreads();
#pragma unroll
    for (int stride = 128; stride >= 1; stride >>= 1) {
        if (threadIdx.x < stride) s[threadIdx.x] += s[threadIdx.x + stride];
        __syncthreads();
    }
    if (threadIdx.x == 0) out[0] = s[0] * (1.0f / (float)N_) + g_reg;
}

extern "C" void kernel_launch(void* const* d_in, const int* in_sizes, int n_in,
                              void* d_out, int out_size) {
    const float* y_pred = (const float*)d_in[0];
    const float* points = (const float*)d_in[1];
    // d_in[2] = voxel_grid — unused by the reference math.
    const float* cp     = (const float*)d_in[3];
    float* out = (float*)d_out;

    pad_kernel<<<NVOX / 256, 256>>>(cp);
    reg_kernel<<<1, 32>>>(y_pred);
    refl_kernel<<<NBLOCKS, 256>>>(y_pred, points);
    final_kernel<<<1, 256>>>(out);
}